// round 4
// baseline (speedup 1.0000x reference)
#include <cuda_runtime.h>
#include <math.h>

// ---------------- problem constants ----------------
#define B_    2
#define C_    48
#define T_    16
#define H_    64
#define W_    64
#define N_    65536          // T*H*W per batch
#define HEADS_ 4
#define NSPLIT 128

// ---------------- scratch (static device globals; no allocs) ----------------
__device__ float g_qkv [(size_t)B_*576*N_];
__device__ float g_qkv2[(size_t)B_*576*N_];
__device__ float g_t192[(size_t)B_*192*N_];
__device__ float g_ln  [(size_t)B_*C_*N_];
__device__ float g_part[(size_t)NSPLIT*B_*HEADS_*48*48];
__device__ float g_attn[(size_t)B_*HEADS_*48*48];
__device__ float g_sumsq[(size_t)B_*384];

// ---------------- LayerNorm over channel dim (+ optional sumsq zeroing) ----------------
__global__ void ln_kernel(const float* __restrict__ x, const float* __restrict__ w,
                          const float* __restrict__ b, float* __restrict__ y,
                          float* __restrict__ zerobuf) {
    int idx = blockIdx.x * blockDim.x + threadIdx.x;
    if (zerobuf && idx < B_ * 384) zerobuf[idx] = 0.f;
    if (idx >= B_ * N_) return;
    int bi = idx / N_, n = idx - bi * N_;
    const float* xp = x + (size_t)bi * C_ * N_ + n;
    float v[C_];
    float mu = 0.f;
#pragma unroll
    for (int c = 0; c < C_; c++) { v[c] = xp[(size_t)c * N_]; mu += v[c]; }
    mu *= (1.f / C_);
    float var = 0.f;
#pragma unroll
    for (int c = 0; c < C_; c++) { float d = v[c] - mu; var += d * d; }
    var *= (1.f / C_);
    float inv = rsqrtf(var + 1e-5f);
    float* yp = y + (size_t)bi * C_ * N_ + n;
#pragma unroll
    for (int c = 0; c < C_; c++) yp[(size_t)c * N_] = (v[c] - mu) * inv * w[c] + b[c];
}

// ---------------- 1x1x1 conv: 16 outputs x 2 positions, LDS.128 weights ----------------
template<int CIN>
__global__ void __launch_bounds__(256) conv1x1_kernel(
        const float* __restrict__ in, const float* __restrict__ wgt,
        const float* __restrict__ bias, const float* __restrict__ res,
        float* __restrict__ out, int cout) {
    __shared__ float4 ws4[16 * CIN / 4];
    float* ws = (float*)ws4;
    int tid = threadIdx.x;
    int cb = blockIdx.y * 16;
    int b  = blockIdx.z;
    for (int i = tid; i < 16 * CIN; i += 256)
        ws[i] = wgt[(size_t)(cb + i / CIN) * CIN + (i % CIN)];
    __syncthreads();
    int n0 = (blockIdx.x * 256 + tid) * 2;
    float acc[16][2];
#pragma unroll
    for (int o = 0; o < 16; o++) { float bv = bias[cb + o]; acc[o][0] = acc[o][1] = bv; }
    const float* ip = in + (size_t)b * CIN * N_ + n0;
#pragma unroll 2
    for (int c4 = 0; c4 < CIN / 4; c4++) {
        float2 xv[4];
#pragma unroll
        for (int j = 0; j < 4; j++)
            xv[j] = *reinterpret_cast<const float2*>(ip + (size_t)(c4 * 4 + j) * N_);
#pragma unroll
        for (int o = 0; o < 16; o++) {
            float4 wv = ws4[o * (CIN / 4) + c4];
            acc[o][0] = fmaf(wv.x, xv[0].x, acc[o][0]);
            acc[o][1] = fmaf(wv.x, xv[0].y, acc[o][1]);
            acc[o][0] = fmaf(wv.y, xv[1].x, acc[o][0]);
            acc[o][1] = fmaf(wv.y, xv[1].y, acc[o][1]);
            acc[o][0] = fmaf(wv.z, xv[2].x, acc[o][0]);
            acc[o][1] = fmaf(wv.z, xv[2].y, acc[o][1]);
            acc[o][0] = fmaf(wv.w, xv[3].x, acc[o][0]);
            acc[o][1] = fmaf(wv.w, xv[3].y, acc[o][1]);
        }
    }
    float* op = out + ((size_t)b * cout + cb) * N_ + n0;
    if (res) {
        const float* rp = res + ((size_t)b * cout + cb) * N_ + n0;
#pragma unroll
        for (int o = 0; o < 16; o++) {
            float2 rv = *reinterpret_cast<const float2*>(rp + (size_t)o * N_);
            *reinterpret_cast<float2*>(op + (size_t)o * N_) =
                make_float2(acc[o][0] + rv.x, acc[o][1] + rv.y);
        }
    } else {
#pragma unroll
        for (int o = 0; o < 16; o++)
            *reinterpret_cast<float2*>(op + (size_t)o * N_) = make_float2(acc[o][0], acc[o][1]);
    }
}

// ---------------- grouped 3x3x3 conv (576 ch): 2 output channels per thread ----------------
// block = one (b, o-pair, t); 256 threads, each a 4x4 spatial tile for BOTH o channels.
__global__ void __launch_bounds__(256) gdw576_kernel(
        const float* __restrict__ in, const float* __restrict__ wgt,
        const float* __restrict__ bias, float* __restrict__ out,
        float* __restrict__ sumsq) {
    int tid = threadIdx.x;
    int wq = tid & 15, hq = tid >> 4;       // 16x16 tiles of 4x4 over 64x64
    int bidx = blockIdx.x;                  // B * 288 * 16
    int t  = bidx & 15;
    int op = (bidx >> 4) % 288;
    int b  = bidx / (16 * 288);
    int g  = op >> 1;
    int o0 = g * 4 + (op & 1) * 2;          // pair (o0, o0+1), same group
    int cbase = g * 4;
    int w0 = wq * 4, h0 = hq * 4;

    float acc[2][16];
    {
        float b0 = bias[o0], b1 = bias[o0 + 1];
#pragma unroll
        for (int i = 0; i < 16; i++) { acc[0][i] = b0; acc[1][i] = b1; }
    }

#pragma unroll 1
    for (int ci = 0; ci < 4; ci++) {
        const float* ip = in + (size_t)(b * 576 + cbase + ci) * (T_ * H_ * W_);
        const float* wp0 = wgt + (size_t)(o0 * 4 + ci) * 27;
        const float* wp1 = wgt + (size_t)((o0 + 1) * 4 + ci) * 27;
#pragma unroll
        for (int kd = 0; kd < 3; kd++) {
            int tt = t + kd - 1;
            if ((unsigned)tt >= (unsigned)T_) continue;
            float wk0[9], wk1[9];
#pragma unroll
            for (int j = 0; j < 9; j++) { wk0[j] = wp0[kd * 9 + j]; wk1[j] = wp1[kd * 9 + j]; }
            const float* pl = ip + (size_t)tt * H_ * W_;
#pragma unroll
            for (int r = 0; r < 6; r++) {
                int hh = h0 - 1 + r;
                if ((unsigned)hh >= (unsigned)H_) continue;
                const float* rowp = pl + hh * W_ + w0;
                float v[6];
#pragma unroll
                for (int j = 0; j < 6; j++) {
                    int ww = w0 - 1 + j;
                    v[j] = ((unsigned)ww < (unsigned)W_) ? rowp[j - 1] : 0.f;
                }
#pragma unroll
                for (int kh = 0; kh < 3; kh++) {
                    int oh = r - kh;
                    if (oh < 0 || oh > 3) continue;   // compile-time
                    float a0 = wk0[kh * 3 + 0], a1 = wk0[kh * 3 + 1], a2 = wk0[kh * 3 + 2];
                    float c0 = wk1[kh * 3 + 0], c1 = wk1[kh * 3 + 1], c2 = wk1[kh * 3 + 2];
#pragma unroll
                    for (int ow = 0; ow < 4; ow++) {
                        acc[0][oh * 4 + ow] = fmaf(a0, v[ow],
                                              fmaf(a1, v[ow + 1],
                                               fmaf(a2, v[ow + 2], acc[0][oh * 4 + ow])));
                        acc[1][oh * 4 + ow] = fmaf(c0, v[ow],
                                              fmaf(c1, v[ow + 1],
                                               fmaf(c2, v[ow + 2], acc[1][oh * 4 + ow])));
                    }
                }
            }
        }
    }

#pragma unroll
    for (int s = 0; s < 2; s++) {
        int o = o0 + s;
        float* opd = out + ((size_t)(b * 576 + o) * T_ + t) * H_ * W_;
        float ssq = 0.f;
#pragma unroll
        for (int oh = 0; oh < 4; oh++) {
            float v0 = acc[s][oh * 4 + 0], v1 = acc[s][oh * 4 + 1];
            float v2 = acc[s][oh * 4 + 2], v3 = acc[s][oh * 4 + 3];
            *reinterpret_cast<float4*>(opd + (h0 + oh) * W_ + w0) = make_float4(v0, v1, v2, v3);
            ssq += v0 * v0 + v1 * v1 + v2 * v2 + v3 * v3;
        }
        if (o < 384) atomicAdd(&sumsq[b * 384 + o], ssq);
    }
}

// ---------------- FFN depthwise 3x3x3 + GELU gate fused (scalar) ----------------
__global__ void __launch_bounds__(256) ffn_dw_gate_kernel(
        const float* __restrict__ in,   // 192 channels
        const float* __restrict__ wgt, const float* __restrict__ bias,
        float* __restrict__ out) {      // 96 channels (gated)
    int tid = threadIdx.x;
    int wq = tid & 15, hq = tid >> 4;
    int bidx = blockIdx.x;                  // B * 96 * 16
    int t = bidx & 15;
    int c = (bidx >> 4) % 96;
    int b = bidx / (16 * 96);
    int w0 = wq * 4, h0 = hq * 4;

    float acc[2][16];
    {
        float b1 = bias[c], b2 = bias[c + 96];
#pragma unroll
        for (int i = 0; i < 16; i++) { acc[0][i] = b1; acc[1][i] = b2; }
    }

#pragma unroll
    for (int s = 0; s < 2; s++) {
        int ch = c + 96 * s;
        const float* ip = in + (size_t)(b * 192 + ch) * (T_ * H_ * W_);
        const float* wp = wgt + (size_t)ch * 27;
#pragma unroll
        for (int kd = 0; kd < 3; kd++) {
            int tt = t + kd - 1;
            if ((unsigned)tt >= (unsigned)T_) continue;
            float wk[9];
#pragma unroll
            for (int j = 0; j < 9; j++) wk[j] = wp[kd * 9 + j];
            const float* pl = ip + (size_t)tt * H_ * W_;
#pragma unroll
            for (int r = 0; r < 6; r++) {
                int hh = h0 - 1 + r;
                if ((unsigned)hh >= (unsigned)H_) continue;
                const float* rowp = pl + hh * W_ + w0;
                float v[6];
#pragma unroll
                for (int j = 0; j < 6; j++) {
                    int ww = w0 - 1 + j;
                    v[j] = ((unsigned)ww < (unsigned)W_) ? rowp[j - 1] : 0.f;
                }
#pragma unroll
                for (int kh = 0; kh < 3; kh++) {
                    int oh = r - kh;
                    if (oh < 0 || oh > 3) continue;
                    float a0 = wk[kh * 3 + 0], a1 = wk[kh * 3 + 1], a2 = wk[kh * 3 + 2];
#pragma unroll
                    for (int ow = 0; ow < 4; ow++)
                        acc[s][oh * 4 + ow] = fmaf(a0, v[ow],
                                               fmaf(a1, v[ow + 1],
                                                fmaf(a2, v[ow + 2], acc[s][oh * 4 + ow])));
                }
            }
        }
    }

    float* opd = out + ((size_t)(b * 96 + c) * T_ + t) * H_ * W_;
#pragma unroll
    for (int oh = 0; oh < 4; oh++) {
        float gv[4];
#pragma unroll
        for (int ow = 0; ow < 4; ow++) {
            float a = acc[0][oh * 4 + ow];
            gv[ow] = 0.5f * a * (1.f + erff(a * 0.70710678118654752f)) * acc[1][oh * 4 + ow];
        }
        *reinterpret_cast<float4*>(opd + (h0 + oh) * W_ + w0) =
            make_float4(gv[0], gv[1], gv[2], gv[3]);
    }
}

// ---------------- q·k^T partials: 48x48 over a 512-slice of N, reg-prefetch pipeline ----------
__global__ void __launch_bounds__(256) qk_kernel(const float* __restrict__ qkv2,
                                                 float* __restrict__ part) {
    __shared__ float qs[48][36];
    __shared__ float ks[48][36];
    int ns = blockIdx.x, h = blockIdx.y, b = blockIdx.z;
    int tid = threadIdx.x;
    int tx = tid & 15, ty = tid >> 4;
    int c0 = tx * 3, d0 = ty * 3;
    const float* qbase = qkv2 + (size_t)(b * 576 + h * 48) * N_;
    const float* kbase = qkv2 + (size_t)(b * 576 + 192 + h * 48) * N_;
    int nbase = ns * (N_ / NSPLIT);          // 512 positions per block

    // 768 float4 items per 32-wide chunk: (q/k, c, nn4); 3 per thread
    int iqk[3], ic[3], in4[3];
#pragma unroll
    for (int j = 0; j < 3; j++) {
        int idx = j * 256 + tid;
        iqk[j] = idx / 384;
        int rem = idx % 384;
        ic[j] = rem >> 3;
        in4[j] = rem & 7;
    }
    float acc[3][3] = {};
    float4 rbuf[3], rnext[3];
#pragma unroll
    for (int j = 0; j < 3; j++) {
        const float* base = iqk[j] ? kbase : qbase;
        rbuf[j] = *reinterpret_cast<const float4*>(base + (size_t)ic[j] * N_ + nbase + in4[j] * 4);
        rnext[j] = rbuf[j];
    }

    for (int ch = 0; ch < 16; ch++) {
#pragma unroll
        for (int j = 0; j < 3; j++) {
            float* dst = (iqk[j] ? &ks[0][0] : &qs[0][0]) + ic[j] * 36 + in4[j] * 4;
            *reinterpret_cast<float4*>(dst) = rbuf[j];
        }
        __syncthreads();
        if (ch < 15) {
            int off = (ch + 1) * 32;
#pragma unroll
            for (int j = 0; j < 3; j++) {
                const float* base = iqk[j] ? kbase : qbase;
                rnext[j] = *reinterpret_cast<const float4*>(
                    base + (size_t)ic[j] * N_ + nbase + off + in4[j] * 4);
            }
        }
#pragma unroll
        for (int nn = 0; nn < 32; nn += 2) {
            float2 q0 = *reinterpret_cast<const float2*>(&qs[c0 + 0][nn]);
            float2 q1 = *reinterpret_cast<const float2*>(&qs[c0 + 1][nn]);
            float2 q2 = *reinterpret_cast<const float2*>(&qs[c0 + 2][nn]);
            float2 k0 = *reinterpret_cast<const float2*>(&ks[d0 + 0][nn]);
            float2 k1 = *reinterpret_cast<const float2*>(&ks[d0 + 1][nn]);
            float2 k2 = *reinterpret_cast<const float2*>(&ks[d0 + 2][nn]);
            acc[0][0] = fmaf(q0.x, k0.x, fmaf(q0.y, k0.y, acc[0][0]));
            acc[0][1] = fmaf(q0.x, k1.x, fmaf(q0.y, k1.y, acc[0][1]));
            acc[0][2] = fmaf(q0.x, k2.x, fmaf(q0.y, k2.y, acc[0][2]));
            acc[1][0] = fmaf(q1.x, k0.x, fmaf(q1.y, k0.y, acc[1][0]));
            acc[1][1] = fmaf(q1.x, k1.x, fmaf(q1.y, k1.y, acc[1][1]));
            acc[1][2] = fmaf(q1.x, k2.x, fmaf(q1.y, k2.y, acc[1][2]));
            acc[2][0] = fmaf(q2.x, k0.x, fmaf(q2.y, k0.y, acc[2][0]));
            acc[2][1] = fmaf(q2.x, k1.x, fmaf(q2.y, k1.y, acc[2][1]));
            acc[2][2] = fmaf(q2.x, k2.x, fmaf(q2.y, k2.y, acc[2][2]));
        }
        __syncthreads();
#pragma unroll
        for (int j = 0; j < 3; j++) rbuf[j] = rnext[j];
    }

    float* pp = part + (((size_t)ns * B_ + b) * HEADS_ + h) * 2304;
#pragma unroll
    for (int i = 0; i < 3; i++)
#pragma unroll
        for (int j = 0; j < 3; j++) pp[(c0 + i) * 48 + d0 + j] = acc[i][j];
}

// ---------------- reduce partials, scale by rsqrt(sumsq) & temperature, softmax ----------------
__global__ void softmax_kernel(const float* __restrict__ part, const float* __restrict__ sumsq,
                               const float* __restrict__ temp, float* __restrict__ attn) {
    int c = blockIdx.x, h = blockIdx.y, b = blockIdx.z;
    int d = threadIdx.x;
    __shared__ float sv[48];
    __shared__ float m_s, sum_s;
    float s = 0.f;
    if (d < 48) {
        const float* pp = part + ((size_t)b * HEADS_ + h) * 2304 + c * 48 + d;
        const size_t stride = (size_t)B_ * HEADS_ * 2304;
        for (int p = 0; p < NSPLIT; p++) s += pp[(size_t)p * stride];
        float rq = 1.f / fmaxf(sqrtf(sumsq[b * 384 + h * 48 + c]), 1e-12f);
        float rk = 1.f / fmaxf(sqrtf(sumsq[b * 384 + 192 + h * 48 + d]), 1e-12f);
        s *= rq * rk * temp[h];
        sv[d] = s;
    }
    __syncthreads();
    if (threadIdx.x == 0) {
        float m = sv[0];
        for (int i = 1; i < 48; i++) m = fmaxf(m, sv[i]);
        m_s = m;
    }
    __syncthreads();
    float e = 0.f;
    if (d < 48) { e = expf(s - m_s); sv[d] = e; }
    __syncthreads();
    if (threadIdx.x == 0) {
        float t2 = 0.f;
        for (int i = 0; i < 48; i++) t2 += sv[i];
        sum_s = t2;
    }
    __syncthreads();
    if (d < 48) attn[(((size_t)b * HEADS_ + h) * 48 + c) * 48 + d] = e / sum_s;
}

// ---------------- out = attn @ v  (transposed attn in smem, broadcast LDS.128) ----------------
__global__ void __launch_bounds__(256) av_kernel(const float* __restrict__ qkv2,
                                                 const float* __restrict__ attn,
                                                 float* __restrict__ out) {
    __shared__ float at[48][48];            // [d][c], rows 192B -> float4-aligned
    int h = blockIdx.y, b = blockIdx.z;
    int tid = threadIdx.x;
    for (int i = tid; i < 2304; i += 256) {
        int c = i / 48, d = i - c * 48;
        at[d][c] = attn[((size_t)b * HEADS_ + h) * 2304 + i];
    }
    __syncthreads();
    int n = blockIdx.x * 256 + tid;
    const float* vb = qkv2 + (size_t)(b * 576 + 384 + h * 48) * N_ + n;
    float acc[48] = {};
#pragma unroll 4
    for (int d = 0; d < 48; d++) {
        float v = vb[(size_t)d * N_];
        const float4* ar = reinterpret_cast<const float4*>(&at[d][0]);
#pragma unroll
        for (int c4 = 0; c4 < 12; c4++) {
            float4 a = ar[c4];
            acc[c4 * 4 + 0] = fmaf(a.x, v, acc[c4 * 4 + 0]);
            acc[c4 * 4 + 1] = fmaf(a.y, v, acc[c4 * 4 + 1]);
            acc[c4 * 4 + 2] = fmaf(a.z, v, acc[c4 * 4 + 2]);
            acc[c4 * 4 + 3] = fmaf(a.w, v, acc[c4 * 4 + 3]);
        }
    }
    float* op = out + (size_t)(b * 192 + h * 48) * N_ + n;
#pragma unroll
    for (int c = 0; c < 48; c++) op[(size_t)c * N_] = acc[c];
}

// ---------------- launcher ----------------
extern "C" void kernel_launch(void* const* d_in, const int* in_sizes, int n_in,
                              void* d_out, int out_size) {
    (void)in_sizes; (void)n_in; (void)out_size;
    const float* x      = (const float*)d_in[0];
    const float* ln1_w  = (const float*)d_in[1];
    const float* ln1_b  = (const float*)d_in[2];
    const float* qkv_w  = (const float*)d_in[3];
    const float* qkv_b  = (const float*)d_in[4];
    const float* qkvdw_w= (const float*)d_in[5];
    const float* qkvdw_b= (const float*)d_in[6];
    const float* temper = (const float*)d_in[7];
    const float* proj_w = (const float*)d_in[8];
    const float* proj_b = (const float*)d_in[9];
    const float* ln2_w  = (const float*)d_in[10];
    const float* ln2_b  = (const float*)d_in[11];
    const float* pin_w  = (const float*)d_in[12];
    const float* pin_b  = (const float*)d_in[13];
    const float* dw_w   = (const float*)d_in[14];
    const float* dw_b   = (const float*)d_in[15];
    const float* pout_w = (const float*)d_in[16];
    const float* pout_b = (const float*)d_in[17];
    float* out = (float*)d_out;

    float *qkv, *qkv2, *t192, *ln, *part, *attn, *sumsq;
    cudaGetSymbolAddress((void**)&qkv,  g_qkv);
    cudaGetSymbolAddress((void**)&qkv2, g_qkv2);
    cudaGetSymbolAddress((void**)&t192, g_t192);
    cudaGetSymbolAddress((void**)&ln,   g_ln);
    cudaGetSymbolAddress((void**)&part, g_part);
    cudaGetSymbolAddress((void**)&attn, g_attn);
    cudaGetSymbolAddress((void**)&sumsq,g_sumsq);

    // ---- attention branch ----
    ln_kernel<<<(B_ * N_) / 256, 256>>>(x, ln1_w, ln1_b, ln, sumsq);

    conv1x1_kernel<48><<<dim3(N_ / 512, 576 / 16, B_), 256>>>(ln, qkv_w, qkv_b, nullptr, qkv, 576);

    gdw576_kernel<<<B_ * 288 * T_, 256>>>(qkv, qkvdw_w, qkvdw_b, qkv2, sumsq);

    qk_kernel<<<dim3(NSPLIT, HEADS_, B_), 256>>>(qkv2, part);

    softmax_kernel<<<dim3(48, HEADS_, B_), 64>>>(part, sumsq, temper, attn);

    av_kernel<<<dim3(N_ / 256, HEADS_, B_), 256>>>(qkv2, attn, t192);

    conv1x1_kernel<192><<<dim3(N_ / 512, 48 / 16, B_), 256>>>(t192, proj_w, proj_b, x, out, 48);

    // ---- FFN branch ----
    ln_kernel<<<(B_ * N_) / 256, 256>>>(out, ln2_w, ln2_b, ln, nullptr);

    conv1x1_kernel<48><<<dim3(N_ / 512, 192 / 16, B_), 256>>>(ln, pin_w, pin_b, nullptr, t192, 192);

    ffn_dw_gate_kernel<<<B_ * 96 * T_, 256>>>(t192, dw_w, dw_b, qkv);

    conv1x1_kernel<96><<<dim3(N_ / 512, 48 / 16, B_), 256>>>(qkv, pout_w, pout_b, out, out, 48);
}

// round 5
// speedup vs baseline: 1.3347x; 1.3347x over previous
#include <cuda_runtime.h>
#include <math.h>

// ---------------- problem constants ----------------
#define B_    2
#define C_    48
#define T_    16
#define H_    64
#define W_    64
#define N_    65536          // T*H*W per batch
#define HEADS_ 4
#define NSPLIT 128

// ---------------- scratch (static device globals; no allocs) ----------------
__device__ float g_qkv [(size_t)B_*576*N_];
__device__ float g_qkv2[(size_t)B_*576*N_];
__device__ float g_t192[(size_t)B_*192*N_];
__device__ float g_ln  [(size_t)B_*C_*N_];
__device__ float g_part[(size_t)NSPLIT*B_*HEADS_*48*48];
__device__ float g_attn[(size_t)B_*HEADS_*48*48];
__device__ float g_inv [(size_t)B_*384];

// ---------------- dummy (profiling alignment: makes gdw576 the 4th launch) ----------
__global__ void zero_kernel(float* __restrict__ p, int n) {
    int i = blockIdx.x * blockDim.x + threadIdx.x;
    if (i < n) p[i] = 0.f;
}

// ---------------- LayerNorm over channel dim ----------------
__global__ void ln_kernel(const float* __restrict__ x, const float* __restrict__ w,
                          const float* __restrict__ b, float* __restrict__ y) {
    int idx = blockIdx.x * blockDim.x + threadIdx.x;
    if (idx >= B_ * N_) return;
    int bi = idx / N_, n = idx - bi * N_;
    const float* xp = x + (size_t)bi * C_ * N_ + n;
    float v[C_];
    float mu = 0.f;
#pragma unroll
    for (int c = 0; c < C_; c++) { v[c] = xp[(size_t)c * N_]; mu += v[c]; }
    mu *= (1.f / C_);
    float var = 0.f;
#pragma unroll
    for (int c = 0; c < C_; c++) { float d = v[c] - mu; var += d * d; }
    var *= (1.f / C_);
    float inv = rsqrtf(var + 1e-5f);
    float* yp = y + (size_t)bi * C_ * N_ + n;
#pragma unroll
    for (int c = 0; c < C_; c++) yp[(size_t)c * N_] = (v[c] - mu) * inv * w[c] + b[c];
}

// ---------------- 1x1x1 conv (pointwise GEMM)  [r1 version] ----------------
template<int CIN, int CO_TILE>
__global__ void conv1x1_kernel(const float* __restrict__ in, const float* __restrict__ wgt,
                               const float* __restrict__ bias, const float* __restrict__ res,
                               float* __restrict__ out, int cout) {
    __shared__ float ws[CO_TILE * CIN];
    __shared__ float bs[CO_TILE];
    int tid = threadIdx.x;
    int cb = blockIdx.y * CO_TILE;
    int b  = blockIdx.z;
    for (int i = tid; i < CO_TILE * CIN; i += blockDim.x)
        ws[i] = wgt[(size_t)(cb + i / CIN) * CIN + (i % CIN)];
    for (int i = tid; i < CO_TILE; i += blockDim.x) bs[i] = bias[cb + i];
    __syncthreads();
    int n = blockIdx.x * blockDim.x + tid;
    float acc[CO_TILE];
#pragma unroll
    for (int o = 0; o < CO_TILE; o++) acc[o] = bs[o];
    const float* ip = in + (size_t)b * CIN * N_ + n;
#pragma unroll 4
    for (int c = 0; c < CIN; c++) {
        float xv = ip[(size_t)c * N_];
#pragma unroll
        for (int o = 0; o < CO_TILE; o++) acc[o] = fmaf(ws[o * CIN + c], xv, acc[o]);
    }
    float* op = out + ((size_t)b * cout + cb) * N_ + n;
    if (res) {
        const float* rp = res + ((size_t)b * cout + cb) * N_ + n;
#pragma unroll
        for (int o = 0; o < CO_TILE; o++) op[(size_t)o * N_] = acc[o] + rp[(size_t)o * N_];
    } else {
#pragma unroll
        for (int o = 0; o < CO_TILE; o++) op[(size_t)o * N_] = acc[o];
    }
}

// ---------------- grouped 3x3x3 conv, pad=1  [r1 version] ----------------
template<int CHTOT, int CIPG, int COPG>
__global__ void gdw_kernel(const float* __restrict__ in, const float* __restrict__ wgt,
                           const float* __restrict__ bias, float* __restrict__ out) {
    long idx = (long)blockIdx.x * blockDim.x + threadIdx.x;
    const long total = (long)B_ * CHTOT * T_ * 16 * 16;
    if (idx >= total) return;
    int wq = (int)(idx & 15);
    long rest = idx >> 4;
    int hq = (int)(rest & 15); rest >>= 4;
    int t  = (int)(rest & 15); rest >>= 4;
    int o  = (int)(rest % CHTOT);
    int b  = (int)(rest / CHTOT);
    int w0 = wq * 4, h0 = hq * 4;
    int cbase = (o / COPG) * CIPG;

    float bv = bias[o];
    float acc[4][4];
#pragma unroll
    for (int i = 0; i < 4; i++)
#pragma unroll
        for (int j = 0; j < 4; j++) acc[i][j] = bv;

    const float* wb = wgt + (size_t)o * CIPG * 27;
#pragma unroll
    for (int ci = 0; ci < CIPG; ci++) {
        float wk[27];
#pragma unroll
        for (int k = 0; k < 27; k++) wk[k] = wb[ci * 27 + k];
        const float* ip = in + (size_t)(b * CHTOT + cbase + ci) * T_ * H_ * W_;
#pragma unroll
        for (int kd = 0; kd < 3; kd++) {
            int tt = t + kd - 1;
            if ((unsigned)tt < (unsigned)T_) {
                const float* pl = ip + (size_t)tt * H_ * W_;
#pragma unroll
                for (int r = 0; r < 6; r++) {
                    int hh = h0 - 1 + r;
                    if ((unsigned)hh < (unsigned)H_) {
                        const float* rowp = pl + hh * W_;
                        float v[6];
#pragma unroll
                        for (int j = 0; j < 6; j++) {
                            int ww = w0 - 1 + j;
                            v[j] = ((unsigned)ww < (unsigned)W_) ? rowp[ww] : 0.f;
                        }
#pragma unroll
                        for (int kh = 0; kh < 3; kh++) {
                            int oh = r - kh;
                            if (oh >= 0 && oh < 4) {
                                float k0 = wk[kd * 9 + kh * 3 + 0];
                                float k1 = wk[kd * 9 + kh * 3 + 1];
                                float k2 = wk[kd * 9 + kh * 3 + 2];
#pragma unroll
                                for (int ow = 0; ow < 4; ow++)
                                    acc[oh][ow] = fmaf(k0, v[ow],
                                                   fmaf(k1, v[ow + 1],
                                                    fmaf(k2, v[ow + 2], acc[oh][ow])));
                            }
                        }
                    }
                }
            }
        }
    }
    float* op = out + ((size_t)(b * CHTOT + o) * T_ + t) * H_ * W_;
#pragma unroll
    for (int i = 0; i < 4; i++)
#pragma unroll
        for (int j = 0; j < 4; j++) op[(h0 + i) * W_ + w0 + j] = acc[i][j];
}

// ---------------- per-row L2 norm (q and k rows)  [r1 version] ----------------
__global__ void rownorm_kernel(const float* __restrict__ qkv2, float* __restrict__ inv) {
    int row = blockIdx.x;              // 0 .. B_*384-1
    int b = row / 384, ch = row % 384;
    const float* p = qkv2 + (size_t)(b * 576 + ch) * N_;
    float s = 0.f;
    for (int n = threadIdx.x; n < N_; n += blockDim.x) { float v = p[n]; s += v * v; }
    __shared__ float red[256];
    red[threadIdx.x] = s;
    __syncthreads();
    for (int off = 128; off; off >>= 1) {
        if (threadIdx.x < off) red[threadIdx.x] += red[threadIdx.x + off];
        __syncthreads();
    }
    if (threadIdx.x == 0) inv[row] = 1.f / fmaxf(sqrtf(red[0]), 1e-12f);
}

// ---------------- q·k^T partials: 512-slice, reg-prefetch pipeline  [r4, measured 88us] ----
__global__ void __launch_bounds__(256) qk_kernel(const float* __restrict__ qkv2,
                                                 float* __restrict__ part) {
    __shared__ float qs[48][36];
    __shared__ float ks[48][36];
    int ns = blockIdx.x, h = blockIdx.y, b = blockIdx.z;
    int tid = threadIdx.x;
    int tx = tid & 15, ty = tid >> 4;
    int c0 = tx * 3, d0 = ty * 3;
    const float* qbase = qkv2 + (size_t)(b * 576 + h * 48) * N_;
    const float* kbase = qkv2 + (size_t)(b * 576 + 192 + h * 48) * N_;
    int nbase = ns * (N_ / NSPLIT);          // 512 positions per block

    int iqk[3], ic[3], in4[3];
#pragma unroll
    for (int j = 0; j < 3; j++) {
        int idx = j * 256 + tid;
        iqk[j] = idx / 384;
        int rem = idx % 384;
        ic[j] = rem >> 3;
        in4[j] = rem & 7;
    }
    float acc[3][3] = {};
    float4 rbuf[3], rnext[3];
#pragma unroll
    for (int j = 0; j < 3; j++) {
        const float* base = iqk[j] ? kbase : qbase;
        rbuf[j] = *reinterpret_cast<const float4*>(base + (size_t)ic[j] * N_ + nbase + in4[j] * 4);
        rnext[j] = rbuf[j];
    }

    for (int ch = 0; ch < 16; ch++) {
#pragma unroll
        for (int j = 0; j < 3; j++) {
            float* dst = (iqk[j] ? &ks[0][0] : &qs[0][0]) + ic[j] * 36 + in4[j] * 4;
            *reinterpret_cast<float4*>(dst) = rbuf[j];
        }
        __syncthreads();
        if (ch < 15) {
            int off = (ch + 1) * 32;
#pragma unroll
            for (int j = 0; j < 3; j++) {
                const float* base = iqk[j] ? kbase : qbase;
                rnext[j] = *reinterpret_cast<const float4*>(
                    base + (size_t)ic[j] * N_ + nbase + off + in4[j] * 4);
            }
        }
#pragma unroll
        for (int nn = 0; nn < 32; nn += 2) {
            float2 q0 = *reinterpret_cast<const float2*>(&qs[c0 + 0][nn]);
            float2 q1 = *reinterpret_cast<const float2*>(&qs[c0 + 1][nn]);
            float2 q2 = *reinterpret_cast<const float2*>(&qs[c0 + 2][nn]);
            float2 k0 = *reinterpret_cast<const float2*>(&ks[d0 + 0][nn]);
            float2 k1 = *reinterpret_cast<const float2*>(&ks[d0 + 1][nn]);
            float2 k2 = *reinterpret_cast<const float2*>(&ks[d0 + 2][nn]);
            acc[0][0] = fmaf(q0.x, k0.x, fmaf(q0.y, k0.y, acc[0][0]));
            acc[0][1] = fmaf(q0.x, k1.x, fmaf(q0.y, k1.y, acc[0][1]));
            acc[0][2] = fmaf(q0.x, k2.x, fmaf(q0.y, k2.y, acc[0][2]));
            acc[1][0] = fmaf(q1.x, k0.x, fmaf(q1.y, k0.y, acc[1][0]));
            acc[1][1] = fmaf(q1.x, k1.x, fmaf(q1.y, k1.y, acc[1][1]));
            acc[1][2] = fmaf(q1.x, k2.x, fmaf(q1.y, k2.y, acc[1][2]));
            acc[2][0] = fmaf(q2.x, k0.x, fmaf(q2.y, k0.y, acc[2][0]));
            acc[2][1] = fmaf(q2.x, k1.x, fmaf(q2.y, k1.y, acc[2][1]));
            acc[2][2] = fmaf(q2.x, k2.x, fmaf(q2.y, k2.y, acc[2][2]));
        }
        __syncthreads();
#pragma unroll
        for (int j = 0; j < 3; j++) rbuf[j] = rnext[j];
    }

    float* pp = part + (((size_t)ns * B_ + b) * HEADS_ + h) * 2304;
#pragma unroll
    for (int i = 0; i < 3; i++)
#pragma unroll
        for (int j = 0; j < 3; j++) pp[(c0 + i) * 48 + d0 + j] = acc[i][j];
}

// ---------------- reduce partials, scale by inv norms & temperature, softmax ----------------
__global__ void softmax_kernel(const float* __restrict__ part, const float* __restrict__ inv,
                               const float* __restrict__ temp, float* __restrict__ attn) {
    int c = blockIdx.x, h = blockIdx.y, b = blockIdx.z;
    int d = threadIdx.x;
    __shared__ float sv[48];
    __shared__ float m_s, sum_s;
    float s = 0.f;
    if (d < 48) {
        const float* pp = part + ((size_t)b * HEADS_ + h) * 2304 + c * 48 + d;
        const size_t stride = (size_t)B_ * HEADS_ * 2304;
        for (int p = 0; p < NSPLIT; p++) s += pp[(size_t)p * stride];
        s *= inv[b * 384 + h * 48 + c] * inv[b * 384 + 192 + h * 48 + d] * temp[h];
        sv[d] = s;
    }
    __syncthreads();
    if (threadIdx.x == 0) {
        float m = sv[0];
        for (int i = 1; i < 48; i++) m = fmaxf(m, sv[i]);
        m_s = m;
    }
    __syncthreads();
    float e = 0.f;
    if (d < 48) { e = expf(s - m_s); sv[d] = e; }
    __syncthreads();
    if (threadIdx.x == 0) {
        float t2 = 0.f;
        for (int i = 0; i < 48; i++) t2 += sv[i];
        sum_s = t2;
    }
    __syncthreads();
    if (d < 48) attn[(((size_t)b * HEADS_ + h) * 48 + c) * 48 + d] = e / sum_s;
}

// ---------------- out = attn @ v  (transposed attn, broadcast LDS.128)  [r4 version] -------
__global__ void __launch_bounds__(256) av_kernel(const float* __restrict__ qkv2,
                                                 const float* __restrict__ attn,
                                                 float* __restrict__ out) {
    __shared__ float at[48][48];            // [d][c]
    int h = blockIdx.y, b = blockIdx.z;
    int tid = threadIdx.x;
    for (int i = tid; i < 2304; i += 256) {
        int c = i / 48, d = i - c * 48;
        at[d][c] = attn[((size_t)b * HEADS_ + h) * 2304 + i];
    }
    __syncthreads();
    int n = blockIdx.x * 256 + tid;
    const float* vb = qkv2 + (size_t)(b * 576 + 384 + h * 48) * N_ + n;
    float acc[48] = {};
#pragma unroll 4
    for (int d = 0; d < 48; d++) {
        float v = vb[(size_t)d * N_];
        const float4* ar = reinterpret_cast<const float4*>(&at[d][0]);
#pragma unroll
        for (int c4 = 0; c4 < 12; c4++) {
            float4 a = ar[c4];
            acc[c4 * 4 + 0] = fmaf(a.x, v, acc[c4 * 4 + 0]);
            acc[c4 * 4 + 1] = fmaf(a.y, v, acc[c4 * 4 + 1]);
            acc[c4 * 4 + 2] = fmaf(a.z, v, acc[c4 * 4 + 2]);
            acc[c4 * 4 + 3] = fmaf(a.w, v, acc[c4 * 4 + 3]);
        }
    }
    float* op = out + (size_t)(b * 192 + h * 48) * N_ + n;
#pragma unroll
    for (int c = 0; c < 48; c++) op[(size_t)c * N_] = acc[c];
}

// ---------------- GELU(z1) * z2 gate  [r1 version] ----------------
__global__ void gate_kernel(const float* __restrict__ z, float* __restrict__ g) {
    int idx = blockIdx.x * blockDim.x + threadIdx.x;
    if (idx >= B_ * 96 * N_) return;
    int n = idx % N_;
    int rest = idx / N_;
    int c = rest % 96;
    int b = rest / 96;
    float a  = z[(size_t)(b * 192 + c) * N_ + n];
    float b2 = z[(size_t)(b * 192 + 96 + c) * N_ + n];
    float ge = 0.5f * a * (1.f + erff(a * 0.70710678118654752f));
    g[(size_t)(b * 96 + c) * N_ + n] = ge * b2;
}

// ---------------- launcher ----------------
extern "C" void kernel_launch(void* const* d_in, const int* in_sizes, int n_in,
                              void* d_out, int out_size) {
    (void)in_sizes; (void)n_in; (void)out_size;
    const float* x      = (const float*)d_in[0];
    const float* ln1_w  = (const float*)d_in[1];
    const float* ln1_b  = (const float*)d_in[2];
    const float* qkv_w  = (const float*)d_in[3];
    const float* qkv_b  = (const float*)d_in[4];
    const float* qkvdw_w= (const float*)d_in[5];
    const float* qkvdw_b= (const float*)d_in[6];
    const float* temper = (const float*)d_in[7];
    const float* proj_w = (const float*)d_in[8];
    const float* proj_b = (const float*)d_in[9];
    const float* ln2_w  = (const float*)d_in[10];
    const float* ln2_b  = (const float*)d_in[11];
    const float* pin_w  = (const float*)d_in[12];
    const float* pin_b  = (const float*)d_in[13];
    const float* dw_w   = (const float*)d_in[14];
    const float* dw_b   = (const float*)d_in[15];
    const float* pout_w = (const float*)d_in[16];
    const float* pout_b = (const float*)d_in[17];
    float* out = (float*)d_out;

    float *qkv, *qkv2, *t192, *ln, *part, *attn, *inv;
    cudaGetSymbolAddress((void**)&qkv,  g_qkv);
    cudaGetSymbolAddress((void**)&qkv2, g_qkv2);
    cudaGetSymbolAddress((void**)&t192, g_t192);
    cudaGetSymbolAddress((void**)&ln,   g_ln);
    cudaGetSymbolAddress((void**)&part, g_part);
    cudaGetSymbolAddress((void**)&attn, g_attn);
    cudaGetSymbolAddress((void**)&inv,  g_inv);

    // launch 0: dummy (aligns gdw576 to the profiled 4th launch)
    zero_kernel<<<3, 256>>>(inv, B_ * 384);

    // ---- attention branch ----
    ln_kernel<<<(B_ * N_) / 256, 256>>>(x, ln1_w, ln1_b, ln);                                   // 1

    conv1x1_kernel<48, 32><<<dim3(N_ / 256, 576 / 32, B_), 256>>>(ln, qkv_w, qkv_b, nullptr, qkv, 576); // 2

    gdw_kernel<576, 4, 4><<<(B_ * 576 * T_ * 16 * 16) / 128, 128>>>(qkv, qkvdw_w, qkvdw_b, qkv2); // 3 <- profiled

    rownorm_kernel<<<B_ * 384, 256>>>(qkv2, inv);                                               // 4

    qk_kernel<<<dim3(NSPLIT, HEADS_, B_), 256>>>(qkv2, part);                                   // 5

    softmax_kernel<<<dim3(48, HEADS_, B_), 64>>>(part, inv, temper, attn);                      // 6

    av_kernel<<<dim3(N_ / 256, HEADS_, B_), 256>>>(qkv2, attn, t192);                           // 7

    conv1x1_kernel<192, 48><<<dim3(N_ / 256, 1, B_), 256>>>(t192, proj_w, proj_b, x, out, 48);  // 8

    // ---- FFN branch ----
    ln_kernel<<<(B_ * N_) / 256, 256>>>(out, ln2_w, ln2_b, ln);                                 // 9

    conv1x1_kernel<48, 32><<<dim3(N_ / 256, 192 / 32, B_), 256>>>(ln, pin_w, pin_b, nullptr, t192, 192); // 10

    gdw_kernel<192, 1, 1><<<(B_ * 192 * T_ * 16 * 16) / 128, 128>>>(t192, dw_w, dw_b, qkv);     // 11

    gate_kernel<<<(B_ * 96 * N_) / 256, 256>>>(qkv, qkv2);                                      // 12

    conv1x1_kernel<96, 48><<<dim3(N_ / 256, 1, B_), 256>>>(qkv2, pout_w, pout_b, out, out, 48); // 13
}

// round 6
// speedup vs baseline: 2.2135x; 1.6584x over previous
#include <cuda_runtime.h>
#include <math.h>

// ---------------- problem constants ----------------
#define B_    2
#define C_    48
#define T_    16
#define H_    64
#define W_    64
#define N_    65536          // T*H*W per batch
#define HEADS_ 4
#define NSPLIT 128

// ---------------- scratch (static device globals; no allocs) ----------------
__device__ float g_qkv [(size_t)B_*576*N_];
__device__ float g_qkv2[(size_t)B_*576*N_];
__device__ float g_t192[(size_t)B_*192*N_];
__device__ float g_ln  [(size_t)B_*C_*N_];
__device__ float g_part[(size_t)NSPLIT*B_*HEADS_*48*48];
__device__ float g_attn[(size_t)B_*HEADS_*48*48];
__device__ float g_inv [(size_t)B_*384];

// ---------------- dummy (profiling alignment: keeps gdw576 the 4th launch) ----------
__global__ void zero_kernel(float* __restrict__ p, int n) {
    int i = blockIdx.x * blockDim.x + threadIdx.x;
    if (i < n) p[i] = 0.f;
}

// ---------------- LayerNorm over channel dim ----------------
__global__ void ln_kernel(const float* __restrict__ x, const float* __restrict__ w,
                          const float* __restrict__ b, float* __restrict__ y) {
    int idx = blockIdx.x * blockDim.x + threadIdx.x;
    if (idx >= B_ * N_) return;
    int bi = idx / N_, n = idx - bi * N_;
    const float* xp = x + (size_t)bi * C_ * N_ + n;
    float v[C_];
    float mu = 0.f;
#pragma unroll
    for (int c = 0; c < C_; c++) { v[c] = xp[(size_t)c * N_]; mu += v[c]; }
    mu *= (1.f / C_);
    float var = 0.f;
#pragma unroll
    for (int c = 0; c < C_; c++) { float d = v[c] - mu; var += d * d; }
    var *= (1.f / C_);
    float inv = rsqrtf(var + 1e-5f);
    float* yp = y + (size_t)bi * C_ * N_ + n;
#pragma unroll
    for (int c = 0; c < C_; c++) yp[(size_t)c * N_] = (v[c] - mu) * inv * w[c] + b[c];
}

// ---------------- 1x1x1 conv: transposed smem weights, LDS.128 reads ----------------
template<int CIN, int CO_TILE>
__global__ void conv1x1_kernel(const float* __restrict__ in, const float* __restrict__ wgt,
                               const float* __restrict__ bias, const float* __restrict__ res,
                               float* __restrict__ out, int cout) {
    __shared__ float ws[CIN][CO_TILE];     // c-major: o contiguous -> LDS.128
    __shared__ float bs[CO_TILE];
    int tid = threadIdx.x;
    int cb = blockIdx.y * CO_TILE;
    int b  = blockIdx.z;
    for (int i = tid; i < CO_TILE * CIN; i += blockDim.x) {
        int o = i / CIN, c = i % CIN;
        ws[c][o] = wgt[(size_t)(cb + o) * CIN + c];
    }
    for (int i = tid; i < CO_TILE; i += blockDim.x) bs[i] = bias[cb + i];
    __syncthreads();
    int n = blockIdx.x * blockDim.x + tid;
    float acc[CO_TILE];
#pragma unroll
    for (int o = 0; o < CO_TILE; o++) acc[o] = bs[o];
    const float* ip = in + (size_t)b * CIN * N_ + n;
#pragma unroll 4
    for (int c = 0; c < CIN; c++) {
        float xv = ip[(size_t)c * N_];
        const float4* wr = reinterpret_cast<const float4*>(&ws[c][0]);
#pragma unroll
        for (int o4 = 0; o4 < CO_TILE / 4; o4++) {
            float4 wv = wr[o4];
            acc[o4 * 4 + 0] = fmaf(wv.x, xv, acc[o4 * 4 + 0]);
            acc[o4 * 4 + 1] = fmaf(wv.y, xv, acc[o4 * 4 + 1]);
            acc[o4 * 4 + 2] = fmaf(wv.z, xv, acc[o4 * 4 + 2]);
            acc[o4 * 4 + 3] = fmaf(wv.w, xv, acc[o4 * 4 + 3]);
        }
    }
    float* op = out + ((size_t)b * cout + cb) * N_ + n;
    if (res) {
        const float* rp = res + ((size_t)b * cout + cb) * N_ + n;
#pragma unroll
        for (int o = 0; o < CO_TILE; o++) op[(size_t)o * N_] = acc[o] + rp[(size_t)o * N_];
    } else {
#pragma unroll
        for (int o = 0; o < CO_TILE; o++) op[(size_t)o * N_] = acc[o];
    }
}

// ---------------- grouped 3x3x3 conv (576ch): whole group (4 out ch) per thread ---------
// block = (b, g, t, h-half), 256 threads; each thread: 2h x 4w tile for 4 output channels.
// Loads: 1 LDG.128 per row + shuffle halo; 4x load reuse across the group's outputs.
__global__ void __launch_bounds__(256) gdw576_kernel(
        const float* __restrict__ in, const float* __restrict__ wgt,
        const float* __restrict__ bias, float* __restrict__ out) {
    __shared__ float ws[4 * 3 * 36];       // [ci][kd][oc*9+j]
    int tid = threadIdx.x;
    int bidx = blockIdx.x;                 // B * 144 * 16 * 2
    int hhalf = bidx & 1;
    int t = (bidx >> 1) & 15;
    int g = (bidx >> 5) % 144;
    int b = bidx / (32 * 144);

    // stage group weights: ws[(ci*3+kd)*36 + oc*9 + j] = wgt[((g*4+oc)*4+ci)*27 + kd*9 + j]
    for (int i = tid; i < 432; i += 256) {
        int ci = i / 108, rem = i % 108;
        int kd = rem / 36, r2 = rem % 36;
        int oc = r2 / 9,  jj = r2 % 9;
        ws[i] = wgt[(size_t)((g * 4 + oc) * 4 + ci) * 27 + kd * 9 + jj];
    }
    __syncthreads();

    int wq = tid & 15, hq = tid >> 4;
    int w0 = wq * 4;
    int h0 = hhalf * 32 + hq * 2;

    float acc[4][2][4];
#pragma unroll
    for (int oc = 0; oc < 4; oc++) {
        float bv = bias[g * 4 + oc];
#pragma unroll
        for (int i = 0; i < 2; i++)
#pragma unroll
            for (int j = 0; j < 4; j++) acc[oc][i][j] = bv;
    }

#pragma unroll
    for (int ci = 0; ci < 4; ci++) {
        const float* ip = in + (size_t)(b * 576 + g * 4 + ci) * (T_ * H_ * W_);
#pragma unroll
        for (int kd = 0; kd < 3; kd++) {
            int tt = t + kd - 1;
            if ((unsigned)tt >= (unsigned)T_) continue;   // uniform per block
            float wk[36];
            {
                const float4* wp4 = reinterpret_cast<const float4*>(&ws[(ci * 3 + kd) * 36]);
#pragma unroll
                for (int j4 = 0; j4 < 9; j4++) {
                    float4 wv = wp4[j4];
                    wk[j4 * 4 + 0] = wv.x; wk[j4 * 4 + 1] = wv.y;
                    wk[j4 * 4 + 2] = wv.z; wk[j4 * 4 + 3] = wv.w;
                }
            }
            const float* pl = ip + (size_t)tt * H_ * W_;
#pragma unroll
            for (int r = 0; r < 4; r++) {
                int hh = h0 - 1 + r;
                float4 m = make_float4(0.f, 0.f, 0.f, 0.f);
                if ((unsigned)hh < (unsigned)H_)
                    m = *reinterpret_cast<const float4*>(pl + hh * W_ + w0);
                float e0 = __shfl_up_sync(0xffffffffu, m.w, 1);
                float e5 = __shfl_down_sync(0xffffffffu, m.x, 1);
                if (wq == 0)  e0 = 0.f;
                if (wq == 15) e5 = 0.f;
                float v[6] = { e0, m.x, m.y, m.z, m.w, e5 };
#pragma unroll
                for (int kh = 0; kh < 3; kh++) {
                    int oh = r - kh;
                    if (oh < 0 || oh > 1) continue;       // compile-time
#pragma unroll
                    for (int oc = 0; oc < 4; oc++) {
                        float k0 = wk[oc * 9 + kh * 3 + 0];
                        float k1 = wk[oc * 9 + kh * 3 + 1];
                        float k2 = wk[oc * 9 + kh * 3 + 2];
#pragma unroll
                        for (int ow = 0; ow < 4; ow++)
                            acc[oc][oh][ow] = fmaf(k0, v[ow],
                                               fmaf(k1, v[ow + 1],
                                                fmaf(k2, v[ow + 2], acc[oc][oh][ow])));
                    }
                }
            }
        }
    }

#pragma unroll
    for (int oc = 0; oc < 4; oc++) {
        float* opd = out + ((size_t)(b * 576 + g * 4 + oc) * T_ + t) * H_ * W_;
#pragma unroll
        for (int oh = 0; oh < 2; oh++)
            *reinterpret_cast<float4*>(opd + (h0 + oh) * W_ + w0) =
                make_float4(acc[oc][oh][0], acc[oc][oh][1], acc[oc][oh][2], acc[oc][oh][3]);
    }
}

// ---------------- FFN depthwise 3x3x3 (192 ch): float4 + shuffle halo ----------------
__global__ void __launch_bounds__(256) ffn_dw_kernel(
        const float* __restrict__ in, const float* __restrict__ wgt,
        const float* __restrict__ bias, float* __restrict__ out) {
    long idx = (long)blockIdx.x * 256 + threadIdx.x;
    int wq = (int)(idx & 15);
    long rest = idx >> 4;
    int hq = (int)(rest & 15); rest >>= 4;
    int t  = (int)(rest & 15); rest >>= 4;
    int c  = (int)(rest % 192);
    int b  = (int)(rest / 192);
    int w0 = wq * 4, h0 = hq * 4;

    float bv = bias[c];
    float acc[4][4];
#pragma unroll
    for (int i = 0; i < 4; i++)
#pragma unroll
        for (int j = 0; j < 4; j++) acc[i][j] = bv;

    const float* wb = wgt + (size_t)c * 27;
    const float* ip = in + (size_t)(b * 192 + c) * (T_ * H_ * W_);
#pragma unroll
    for (int kd = 0; kd < 3; kd++) {
        int tt = t + kd - 1;
        if ((unsigned)tt >= (unsigned)T_) continue;       // uniform per warp (t same)
        float wk[9];
#pragma unroll
        for (int j = 0; j < 9; j++) wk[j] = wb[kd * 9 + j];
        const float* pl = ip + (size_t)tt * H_ * W_;
#pragma unroll
        for (int r = 0; r < 6; r++) {
            int hh = h0 - 1 + r;
            float4 m = make_float4(0.f, 0.f, 0.f, 0.f);
            if ((unsigned)hh < (unsigned)H_)
                m = *reinterpret_cast<const float4*>(pl + hh * W_ + w0);
            float e0 = __shfl_up_sync(0xffffffffu, m.w, 1);
            float e5 = __shfl_down_sync(0xffffffffu, m.x, 1);
            if (wq == 0)  e0 = 0.f;
            if (wq == 15) e5 = 0.f;
            float v[6] = { e0, m.x, m.y, m.z, m.w, e5 };
#pragma unroll
            for (int kh = 0; kh < 3; kh++) {
                int oh = r - kh;
                if (oh < 0 || oh > 3) continue;           // compile-time
                float k0 = wk[kh * 3 + 0], k1 = wk[kh * 3 + 1], k2 = wk[kh * 3 + 2];
#pragma unroll
                for (int ow = 0; ow < 4; ow++)
                    acc[oh][ow] = fmaf(k0, v[ow],
                                   fmaf(k1, v[ow + 1],
                                    fmaf(k2, v[ow + 2], acc[oh][ow])));
            }
        }
    }
    float* op = out + ((size_t)(b * 192 + c) * T_ + t) * H_ * W_;
#pragma unroll
    for (int i = 0; i < 4; i++)
        *reinterpret_cast<float4*>(op + (h0 + i) * W_ + w0) =
            make_float4(acc[i][0], acc[i][1], acc[i][2], acc[i][3]);
}

// ---------------- per-row L2 norm (q and k rows) ----------------
__global__ void rownorm_kernel(const float* __restrict__ qkv2, float* __restrict__ inv) {
    int row = blockIdx.x;              // 0 .. B_*384-1
    int b = row / 384, ch = row % 384;
    const float* p = qkv2 + (size_t)(b * 576 + ch) * N_;
    float s = 0.f;
    for (int n = threadIdx.x; n < N_; n += blockDim.x) { float v = p[n]; s += v * v; }
    __shared__ float red[256];
    red[threadIdx.x] = s;
    __syncthreads();
    for (int off = 128; off; off >>= 1) {
        if (threadIdx.x < off) red[threadIdx.x] += red[threadIdx.x + off];
        __syncthreads();
    }
    if (threadIdx.x == 0) inv[row] = 1.f / fmaxf(sqrtf(red[0]), 1e-12f);
}

// ---------------- q·k^T partials: 512-slice, reg-prefetch pipeline ----------------
__global__ void __launch_bounds__(256) qk_kernel(const float* __restrict__ qkv2,
                                                 float* __restrict__ part) {
    __shared__ float qs[48][36];
    __shared__ float ks[48][36];
    int ns = blockIdx.x, h = blockIdx.y, b = blockIdx.z;
    int tid = threadIdx.x;
    int tx = tid & 15, ty = tid >> 4;
    int c0 = tx * 3, d0 = ty * 3;
    const float* qbase = qkv2 + (size_t)(b * 576 + h * 48) * N_;
    const float* kbase = qkv2 + (size_t)(b * 576 + 192 + h * 48) * N_;
    int nbase = ns * (N_ / NSPLIT);

    int iqk[3], ic[3], in4[3];
#pragma unroll
    for (int j = 0; j < 3; j++) {
        int idx = j * 256 + tid;
        iqk[j] = idx / 384;
        int rem = idx % 384;
        ic[j] = rem >> 3;
        in4[j] = rem & 7;
    }
    float acc[3][3] = {};
    float4 rbuf[3], rnext[3];
#pragma unroll
    for (int j = 0; j < 3; j++) {
        const float* base = iqk[j] ? kbase : qbase;
        rbuf[j] = *reinterpret_cast<const float4*>(base + (size_t)ic[j] * N_ + nbase + in4[j] * 4);
        rnext[j] = rbuf[j];
    }

    for (int ch = 0; ch < 16; ch++) {
#pragma unroll
        for (int j = 0; j < 3; j++) {
            float* dst = (iqk[j] ? &ks[0][0] : &qs[0][0]) + ic[j] * 36 + in4[j] * 4;
            *reinterpret_cast<float4*>(dst) = rbuf[j];
        }
        __syncthreads();
        if (ch < 15) {
            int off = (ch + 1) * 32;
#pragma unroll
            for (int j = 0; j < 3; j++) {
                const float* base = iqk[j] ? kbase : qbase;
                rnext[j] = *reinterpret_cast<const float4*>(
                    base + (size_t)ic[j] * N_ + nbase + off + in4[j] * 4);
            }
        }
#pragma unroll
        for (int nn = 0; nn < 32; nn += 2) {
            float2 q0 = *reinterpret_cast<const float2*>(&qs[c0 + 0][nn]);
            float2 q1 = *reinterpret_cast<const float2*>(&qs[c0 + 1][nn]);
            float2 q2 = *reinterpret_cast<const float2*>(&qs[c0 + 2][nn]);
            float2 k0 = *reinterpret_cast<const float2*>(&ks[d0 + 0][nn]);
            float2 k1 = *reinterpret_cast<const float2*>(&ks[d0 + 1][nn]);
            float2 k2 = *reinterpret_cast<const float2*>(&ks[d0 + 2][nn]);
            acc[0][0] = fmaf(q0.x, k0.x, fmaf(q0.y, k0.y, acc[0][0]));
            acc[0][1] = fmaf(q0.x, k1.x, fmaf(q0.y, k1.y, acc[0][1]));
            acc[0][2] = fmaf(q0.x, k2.x, fmaf(q0.y, k2.y, acc[0][2]));
            acc[1][0] = fmaf(q1.x, k0.x, fmaf(q1.y, k0.y, acc[1][0]));
            acc[1][1] = fmaf(q1.x, k1.x, fmaf(q1.y, k1.y, acc[1][1]));
            acc[1][2] = fmaf(q1.x, k2.x, fmaf(q1.y, k2.y, acc[1][2]));
            acc[2][0] = fmaf(q2.x, k0.x, fmaf(q2.y, k0.y, acc[2][0]));
            acc[2][1] = fmaf(q2.x, k1.x, fmaf(q2.y, k1.y, acc[2][1]));
            acc[2][2] = fmaf(q2.x, k2.x, fmaf(q2.y, k2.y, acc[2][2]));
        }
        __syncthreads();
#pragma unroll
        for (int j = 0; j < 3; j++) rbuf[j] = rnext[j];
    }

    float* pp = part + (((size_t)ns * B_ + b) * HEADS_ + h) * 2304;
#pragma unroll
    for (int i = 0; i < 3; i++)
#pragma unroll
        for (int j = 0; j < 3; j++) pp[(c0 + i) * 48 + d0 + j] = acc[i][j];
}

// ---------------- reduce partials, scale by inv norms & temperature, softmax ----------------
__global__ void softmax_kernel(const float* __restrict__ part, const float* __restrict__ inv,
                               const float* __restrict__ temp, float* __restrict__ attn) {
    int c = blockIdx.x, h = blockIdx.y, b = blockIdx.z;
    int d = threadIdx.x;
    __shared__ float sv[48];
    __shared__ float m_s, sum_s;
    float s = 0.f;
    if (d < 48) {
        const float* pp = part + ((size_t)b * HEADS_ + h) * 2304 + c * 48 + d;
        const size_t stride = (size_t)B_ * HEADS_ * 2304;
        for (int p = 0; p < NSPLIT; p++) s += pp[(size_t)p * stride];
        s *= inv[b * 384 + h * 48 + c] * inv[b * 384 + 192 + h * 48 + d] * temp[h];
        sv[d] = s;
    }
    __syncthreads();
    if (threadIdx.x == 0) {
        float m = sv[0];
        for (int i = 1; i < 48; i++) m = fmaxf(m, sv[i]);
        m_s = m;
    }
    __syncthreads();
    float e = 0.f;
    if (d < 48) { e = expf(s - m_s); sv[d] = e; }
    __syncthreads();
    if (threadIdx.x == 0) {
        float t2 = 0.f;
        for (int i = 0; i < 48; i++) t2 += sv[i];
        sum_s = t2;
    }
    __syncthreads();
    if (d < 48) attn[(((size_t)b * HEADS_ + h) * 48 + c) * 48 + d] = e / sum_s;
}

// ---------------- out = attn @ v  (transposed attn, broadcast LDS.128) ----------------
__global__ void __launch_bounds__(256) av_kernel(const float* __restrict__ qkv2,
                                                 const float* __restrict__ attn,
                                                 float* __restrict__ out) {
    __shared__ float at[48][48];            // [d][c]
    int h = blockIdx.y, b = blockIdx.z;
    int tid = threadIdx.x;
    for (int i = tid; i < 2304; i += 256) {
        int c = i / 48, d = i - c * 48;
        at[d][c] = attn[((size_t)b * HEADS_ + h) * 2304 + i];
    }
    __syncthreads();
    int n = blockIdx.x * 256 + tid;
    const float* vb = qkv2 + (size_t)(b * 576 + 384 + h * 48) * N_ + n;
    float acc[48] = {};
#pragma unroll 4
    for (int d = 0; d < 48; d++) {
        float v = vb[(size_t)d * N_];
        const float4* ar = reinterpret_cast<const float4*>(&at[d][0]);
#pragma unroll
        for (int c4 = 0; c4 < 12; c4++) {
            float4 a = ar[c4];
            acc[c4 * 4 + 0] = fmaf(a.x, v, acc[c4 * 4 + 0]);
            acc[c4 * 4 + 1] = fmaf(a.y, v, acc[c4 * 4 + 1]);
            acc[c4 * 4 + 2] = fmaf(a.z, v, acc[c4 * 4 + 2]);
            acc[c4 * 4 + 3] = fmaf(a.w, v, acc[c4 * 4 + 3]);
        }
    }
    float* op = out + (size_t)(b * 192 + h * 48) * N_ + n;
#pragma unroll
    for (int c = 0; c < 48; c++) op[(size_t)c * N_] = acc[c];
}

// ---------------- GELU(z1) * z2 gate ----------------
__global__ void gate_kernel(const float* __restrict__ z, float* __restrict__ g) {
    int idx = blockIdx.x * blockDim.x + threadIdx.x;
    if (idx >= B_ * 96 * N_) return;
    int n = idx % N_;
    int rest = idx / N_;
    int c = rest % 96;
    int b = rest / 96;
    float a  = z[(size_t)(b * 192 + c) * N_ + n];
    float b2 = z[(size_t)(b * 192 + 96 + c) * N_ + n];
    float ge = 0.5f * a * (1.f + erff(a * 0.70710678118654752f));
    g[(size_t)(b * 96 + c) * N_ + n] = ge * b2;
}

// ---------------- launcher ----------------
extern "C" void kernel_launch(void* const* d_in, const int* in_sizes, int n_in,
                              void* d_out, int out_size) {
    (void)in_sizes; (void)n_in; (void)out_size;
    const float* x      = (const float*)d_in[0];
    const float* ln1_w  = (const float*)d_in[1];
    const float* ln1_b  = (const float*)d_in[2];
    const float* qkv_w  = (const float*)d_in[3];
    const float* qkv_b  = (const float*)d_in[4];
    const float* qkvdw_w= (const float*)d_in[5];
    const float* qkvdw_b= (const float*)d_in[6];
    const float* temper = (const float*)d_in[7];
    const float* proj_w = (const float*)d_in[8];
    const float* proj_b = (const float*)d_in[9];
    const float* ln2_w  = (const float*)d_in[10];
    const float* ln2_b  = (const float*)d_in[11];
    const float* pin_w  = (const float*)d_in[12];
    const float* pin_b  = (const float*)d_in[13];
    const float* dw_w   = (const float*)d_in[14];
    const float* dw_b   = (const float*)d_in[15];
    const float* pout_w = (const float*)d_in[16];
    const float* pout_b = (const float*)d_in[17];
    float* out = (float*)d_out;

    float *qkv, *qkv2, *t192, *ln, *part, *attn, *inv;
    cudaGetSymbolAddress((void**)&qkv,  g_qkv);
    cudaGetSymbolAddress((void**)&qkv2, g_qkv2);
    cudaGetSymbolAddress((void**)&t192, g_t192);
    cudaGetSymbolAddress((void**)&ln,   g_ln);
    cudaGetSymbolAddress((void**)&part, g_part);
    cudaGetSymbolAddress((void**)&attn, g_attn);
    cudaGetSymbolAddress((void**)&inv,  g_inv);

    // launch 0: dummy (aligns gdw576 to the profiled 4th launch)
    zero_kernel<<<3, 256>>>(inv, B_ * 384);

    // ---- attention branch ----
    ln_kernel<<<(B_ * N_) / 256, 256>>>(x, ln1_w, ln1_b, ln);                                   // 1

    conv1x1_kernel<48, 32><<<dim3(N_ / 256, 576 / 32, B_), 256>>>(ln, qkv_w, qkv_b, nullptr, qkv, 576); // 2

    gdw576_kernel<<<B_ * 144 * T_ * 2, 256>>>(qkv, qkvdw_w, qkvdw_b, qkv2);                     // 3 <- profiled

    rownorm_kernel<<<B_ * 384, 256>>>(qkv2, inv);                                               // 4

    qk_kernel<<<dim3(NSPLIT, HEADS_, B_), 256>>>(qkv2, part);                                   // 5

    softmax_kernel<<<dim3(48, HEADS_, B_), 64>>>(part, inv, temper, attn);                      // 6

    av_kernel<<<dim3(N_ / 256, HEADS_, B_), 256>>>(qkv2, attn, t192);                           // 7

    conv1x1_kernel<192, 48><<<dim3(N_ / 256, 1, B_), 256>>>(t192, proj_w, proj_b, x, out, 48);  // 8

    // ---- FFN branch ----
    ln_kernel<<<(B_ * N_) / 256, 256>>>(out, ln2_w, ln2_b, ln);                                 // 9

    conv1x1_kernel<48, 32><<<dim3(N_ / 256, 192 / 32, B_), 256>>>(ln, pin_w, pin_b, nullptr, t192, 192); // 10

    ffn_dw_kernel<<<(B_ * 192 * T_ * 16 * 16) / 256, 256>>>(t192, dw_w, dw_b, qkv);             // 11

    gate_kernel<<<(B_ * 96 * N_) / 256, 256>>>(qkv, qkv2);                                      // 12

    conv1x1_kernel<96, 48><<<dim3(N_ / 256, 1, B_), 256>>>(qkv2, pout_w, pout_b, out, out, 48); // 13
}

// round 7
// speedup vs baseline: 2.6032x; 1.1761x over previous
#include <cuda_runtime.h>
#include <math.h>

// ---------------- problem constants ----------------
#define B_    2
#define C_    48
#define T_    16
#define H_    64
#define W_    64
#define N_    65536          // T*H*W per batch
#define HEADS_ 4
#define NSPLIT 128

// ---------------- scratch (static device globals; no allocs) ----------------
__device__ float g_qkv [(size_t)B_*576*N_];
__device__ float g_qkv2[(size_t)B_*576*N_];
__device__ float g_t192[(size_t)B_*192*N_];
__device__ float g_ln  [(size_t)B_*C_*N_];
__device__ float g_part[(size_t)NSPLIT*B_*HEADS_*48*48];
__device__ float g_attn[(size_t)B_*HEADS_*48*48];
__device__ float g_M   [(size_t)B_*192*48];     // proj_w @ attn, [b][hd][co]
__device__ float g_sumsq[(size_t)B_*384];

// ---------------- launch 0: zero sumsq (also keeps gdw576 at profiled slot 3) -------
__global__ void zero_kernel(float* __restrict__ p, int n) {
    int i = blockIdx.x * blockDim.x + threadIdx.x;
    if (i < n) p[i] = 0.f;
}

// ---------------- LayerNorm over channel dim ----------------
__global__ void ln_kernel(const float* __restrict__ x, const float* __restrict__ w,
                          const float* __restrict__ b, float* __restrict__ y) {
    int idx = blockIdx.x * blockDim.x + threadIdx.x;
    if (idx >= B_ * N_) return;
    int bi = idx / N_, n = idx - bi * N_;
    const float* xp = x + (size_t)bi * C_ * N_ + n;
    float v[C_];
    float mu = 0.f;
#pragma unroll
    for (int c = 0; c < C_; c++) { v[c] = xp[(size_t)c * N_]; mu += v[c]; }
    mu *= (1.f / C_);
    float var = 0.f;
#pragma unroll
    for (int c = 0; c < C_; c++) { float d = v[c] - mu; var += d * d; }
    var *= (1.f / C_);
    float inv = rsqrtf(var + 1e-5f);
    float* yp = y + (size_t)bi * C_ * N_ + n;
#pragma unroll
    for (int c = 0; c < C_; c++) yp[(size_t)c * N_] = (v[c] - mu) * inv * w[c] + b[c];
}

// ---------------- 1x1x1 conv: transposed smem weights, LDS.128 reads ----------------
template<int CIN, int CO_TILE>
__global__ void conv1x1_kernel(const float* __restrict__ in, const float* __restrict__ wgt,
                               const float* __restrict__ bias, const float* __restrict__ res,
                               float* __restrict__ out, int cout) {
    __shared__ float ws[CIN][CO_TILE];     // c-major: o contiguous -> LDS.128
    __shared__ float bs[CO_TILE];
    int tid = threadIdx.x;
    int cb = blockIdx.y * CO_TILE;
    int b  = blockIdx.z;
    for (int i = tid; i < CO_TILE * CIN; i += blockDim.x) {
        int o = i / CIN, c = i % CIN;
        ws[c][o] = wgt[(size_t)(cb + o) * CIN + c];
    }
    for (int i = tid; i < CO_TILE; i += blockDim.x) bs[i] = bias[cb + i];
    __syncthreads();
    int n = blockIdx.x * blockDim.x + tid;
    float acc[CO_TILE];
#pragma unroll
    for (int o = 0; o < CO_TILE; o++) acc[o] = bs[o];
    const float* ip = in + (size_t)b * CIN * N_ + n;
#pragma unroll 4
    for (int c = 0; c < CIN; c++) {
        float xv = ip[(size_t)c * N_];
        const float4* wr = reinterpret_cast<const float4*>(&ws[c][0]);
#pragma unroll
        for (int o4 = 0; o4 < CO_TILE / 4; o4++) {
            float4 wv = wr[o4];
            acc[o4 * 4 + 0] = fmaf(wv.x, xv, acc[o4 * 4 + 0]);
            acc[o4 * 4 + 1] = fmaf(wv.y, xv, acc[o4 * 4 + 1]);
            acc[o4 * 4 + 2] = fmaf(wv.z, xv, acc[o4 * 4 + 2]);
            acc[o4 * 4 + 3] = fmaf(wv.w, xv, acc[o4 * 4 + 3]);
        }
    }
    float* op = out + ((size_t)b * cout + cb) * N_ + n;
    if (res) {
        const float* rp = res + ((size_t)b * cout + cb) * N_ + n;
#pragma unroll
        for (int o = 0; o < CO_TILE; o++) op[(size_t)o * N_] = acc[o] + rp[(size_t)o * N_];
    } else {
#pragma unroll
        for (int o = 0; o < CO_TILE; o++) op[(size_t)o * N_] = acc[o];
    }
}

// ---------------- grouped 3x3x3 conv (576ch): whole group per thread, 128-thr blocks ----
// block = (b, g, t, h-quarter); each thread: 2h x 4w tile for the group's 4 output ch.
// Fused: sum-of-squares for q/k channels (warp-reduced atomics).
__global__ void __launch_bounds__(128) gdw576_kernel(
        const float* __restrict__ in, const float* __restrict__ wgt,
        const float* __restrict__ bias, float* __restrict__ out,
        float* __restrict__ sumsq) {
    __shared__ float ws[4 * 3 * 36];       // [ci][kd][oc*9+j]
    int tid = threadIdx.x;
    int bidx = blockIdx.x;                 // B * 144 * 16 * 4
    int hquart = bidx & 3;
    int t = (bidx >> 2) & 15;
    int g = (bidx >> 6) % 144;
    int b = bidx / (64 * 144);

    for (int i = tid; i < 432; i += 128) {
        int ci = i / 108, rem = i % 108;
        int kd = rem / 36, r2 = rem % 36;
        int oc = r2 / 9,  jj = r2 % 9;
        ws[i] = wgt[(size_t)((g * 4 + oc) * 4 + ci) * 27 + kd * 9 + jj];
    }
    __syncthreads();

    int wq = tid & 15, hq = tid >> 4;      // hq 0..7
    int w0 = wq * 4;
    int h0 = hquart * 16 + hq * 2;

    float acc[4][2][4];
#pragma unroll
    for (int oc = 0; oc < 4; oc++) {
        float bv = bias[g * 4 + oc];
#pragma unroll
        for (int i = 0; i < 2; i++)
#pragma unroll
            for (int j = 0; j < 4; j++) acc[oc][i][j] = bv;
    }

#pragma unroll
    for (int ci = 0; ci < 4; ci++) {
        const float* ip = in + (size_t)(b * 576 + g * 4 + ci) * (T_ * H_ * W_);
#pragma unroll
        for (int kd = 0; kd < 3; kd++) {
            int tt = t + kd - 1;
            if ((unsigned)tt >= (unsigned)T_) continue;   // uniform per block
            float wk[36];
            {
                const float4* wp4 = reinterpret_cast<const float4*>(&ws[(ci * 3 + kd) * 36]);
#pragma unroll
                for (int j4 = 0; j4 < 9; j4++) {
                    float4 wv = wp4[j4];
                    wk[j4 * 4 + 0] = wv.x; wk[j4 * 4 + 1] = wv.y;
                    wk[j4 * 4 + 2] = wv.z; wk[j4 * 4 + 3] = wv.w;
                }
            }
            const float* pl = ip + (size_t)tt * H_ * W_;
#pragma unroll
            for (int r = 0; r < 4; r++) {
                int hh = h0 - 1 + r;
                float4 m = make_float4(0.f, 0.f, 0.f, 0.f);
                if ((unsigned)hh < (unsigned)H_)
                    m = *reinterpret_cast<const float4*>(pl + hh * W_ + w0);
                float e0 = __shfl_up_sync(0xffffffffu, m.w, 1);
                float e5 = __shfl_down_sync(0xffffffffu, m.x, 1);
                if (wq == 0)  e0 = 0.f;
                if (wq == 15) e5 = 0.f;
                float v[6] = { e0, m.x, m.y, m.z, m.w, e5 };
#pragma unroll
                for (int kh = 0; kh < 3; kh++) {
                    int oh = r - kh;
                    if (oh < 0 || oh > 1) continue;       // compile-time
#pragma unroll
                    for (int oc = 0; oc < 4; oc++) {
                        float k0 = wk[oc * 9 + kh * 3 + 0];
                        float k1 = wk[oc * 9 + kh * 3 + 1];
                        float k2 = wk[oc * 9 + kh * 3 + 2];
#pragma unroll
                        for (int ow = 0; ow < 4; ow++)
                            acc[oc][oh][ow] = fmaf(k0, v[ow],
                                               fmaf(k1, v[ow + 1],
                                                fmaf(k2, v[ow + 2], acc[oc][oh][ow])));
                    }
                }
            }
        }
    }

    float ssq[4] = {0.f, 0.f, 0.f, 0.f};
#pragma unroll
    for (int oc = 0; oc < 4; oc++) {
        float* opd = out + ((size_t)(b * 576 + g * 4 + oc) * T_ + t) * H_ * W_;
#pragma unroll
        for (int oh = 0; oh < 2; oh++) {
            float v0 = acc[oc][oh][0], v1 = acc[oc][oh][1];
            float v2 = acc[oc][oh][2], v3 = acc[oc][oh][3];
            *reinterpret_cast<float4*>(opd + (h0 + oh) * W_ + w0) = make_float4(v0, v1, v2, v3);
            ssq[oc] += v0 * v0 + v1 * v1 + v2 * v2 + v3 * v3;
        }
    }
    if (g < 96) {   // q/k channels only
#pragma unroll
        for (int oc = 0; oc < 4; oc++) {
#pragma unroll
            for (int off = 16; off; off >>= 1)
                ssq[oc] += __shfl_down_sync(0xffffffffu, ssq[oc], off);
        }
        if ((tid & 31) == 0) {
#pragma unroll
            for (int oc = 0; oc < 4; oc++)
                atomicAdd(&sumsq[b * 384 + g * 4 + oc], ssq[oc]);
        }
    }
}

// ---------------- FFN depthwise 3x3x3 + GELU gate fused ----------------
__global__ void __launch_bounds__(256) ffn_dw_gate_kernel(
        const float* __restrict__ in,   // 192 channels
        const float* __restrict__ wgt, const float* __restrict__ bias,
        float* __restrict__ out) {      // 96 channels (gated)
    long idx = (long)blockIdx.x * 256 + threadIdx.x;
    int wq = (int)(idx & 15);
    long rest = idx >> 4;
    int hq = (int)(rest & 15); rest >>= 4;
    int t  = (int)(rest & 15); rest >>= 4;
    int c  = (int)(rest % 96);
    int b  = (int)(rest / 96);
    int w0 = wq * 4, h0 = hq * 4;

    float acc[2][4][4];
    {
        float b1 = bias[c], b2 = bias[c + 96];
#pragma unroll
        for (int i = 0; i < 4; i++)
#pragma unroll
            for (int j = 0; j < 4; j++) { acc[0][i][j] = b1; acc[1][i][j] = b2; }
    }

#pragma unroll
    for (int s = 0; s < 2; s++) {
        int ch = c + 96 * s;
        const float* wb = wgt + (size_t)ch * 27;
        const float* ip = in + (size_t)(b * 192 + ch) * (T_ * H_ * W_);
#pragma unroll
        for (int kd = 0; kd < 3; kd++) {
            int tt = t + kd - 1;
            if ((unsigned)tt >= (unsigned)T_) continue;
            float wk[9];
#pragma unroll
            for (int j = 0; j < 9; j++) wk[j] = wb[kd * 9 + j];
            const float* pl = ip + (size_t)tt * H_ * W_;
#pragma unroll
            for (int r = 0; r < 6; r++) {
                int hh = h0 - 1 + r;
                float4 m = make_float4(0.f, 0.f, 0.f, 0.f);
                if ((unsigned)hh < (unsigned)H_)
                    m = *reinterpret_cast<const float4*>(pl + hh * W_ + w0);
                float e0 = __shfl_up_sync(0xffffffffu, m.w, 1);
                float e5 = __shfl_down_sync(0xffffffffu, m.x, 1);
                if (wq == 0)  e0 = 0.f;
                if (wq == 15) e5 = 0.f;
                float v[6] = { e0, m.x, m.y, m.z, m.w, e5 };
#pragma unroll
                for (int kh = 0; kh < 3; kh++) {
                    int oh = r - kh;
                    if (oh < 0 || oh > 3) continue;
                    float k0 = wk[kh * 3 + 0], k1 = wk[kh * 3 + 1], k2 = wk[kh * 3 + 2];
#pragma unroll
                    for (int ow = 0; ow < 4; ow++)
                        acc[s][oh][ow] = fmaf(k0, v[ow],
                                          fmaf(k1, v[ow + 1],
                                           fmaf(k2, v[ow + 2], acc[s][oh][ow])));
                }
            }
        }
    }

    float* opd = out + ((size_t)(b * 96 + c) * T_ + t) * H_ * W_;
#pragma unroll
    for (int oh = 0; oh < 4; oh++) {
        float gv[4];
#pragma unroll
        for (int ow = 0; ow < 4; ow++) {
            float a = acc[0][oh][ow];
            gv[ow] = 0.5f * a * (1.f + erff(a * 0.70710678118654752f)) * acc[1][oh][ow];
        }
        *reinterpret_cast<float4*>(opd + (h0 + oh) * W_ + w0) =
            make_float4(gv[0], gv[1], gv[2], gv[3]);
    }
}

// ---------------- q·k^T partials: 512-slice, reg-prefetch pipeline ----------------
__global__ void __launch_bounds__(256) qk_kernel(const float* __restrict__ qkv2,
                                                 float* __restrict__ part) {
    __shared__ float qs[48][36];
    __shared__ float ks[48][36];
    int ns = blockIdx.x, h = blockIdx.y, b = blockIdx.z;
    int tid = threadIdx.x;
    int tx = tid & 15, ty = tid >> 4;
    int c0 = tx * 3, d0 = ty * 3;
    const float* qbase = qkv2 + (size_t)(b * 576 + h * 48) * N_;
    const float* kbase = qkv2 + (size_t)(b * 576 + 192 + h * 48) * N_;
    int nbase = ns * (N_ / NSPLIT);

    int iqk[3], ic[3], in4[3];
#pragma unroll
    for (int j = 0; j < 3; j++) {
        int idx = j * 256 + tid;
        iqk[j] = idx / 384;
        int rem = idx % 384;
        ic[j] = rem >> 3;
        in4[j] = rem & 7;
    }
    float acc[3][3] = {};
    float4 rbuf[3], rnext[3];
#pragma unroll
    for (int j = 0; j < 3; j++) {
        const float* base = iqk[j] ? kbase : qbase;
        rbuf[j] = *reinterpret_cast<const float4*>(base + (size_t)ic[j] * N_ + nbase + in4[j] * 4);
        rnext[j] = rbuf[j];
    }

    for (int ch = 0; ch < 16; ch++) {
#pragma unroll
        for (int j = 0; j < 3; j++) {
            float* dst = (iqk[j] ? &ks[0][0] : &qs[0][0]) + ic[j] * 36 + in4[j] * 4;
            *reinterpret_cast<float4*>(dst) = rbuf[j];
        }
        __syncthreads();
        if (ch < 15) {
            int off = (ch + 1) * 32;
#pragma unroll
            for (int j = 0; j < 3; j++) {
                const float* base = iqk[j] ? kbase : qbase;
                rnext[j] = *reinterpret_cast<const float4*>(
                    base + (size_t)ic[j] * N_ + nbase + off + in4[j] * 4);
            }
        }
#pragma unroll
        for (int nn = 0; nn < 32; nn += 2) {
            float2 q0 = *reinterpret_cast<const float2*>(&qs[c0 + 0][nn]);
            float2 q1 = *reinterpret_cast<const float2*>(&qs[c0 + 1][nn]);
            float2 q2 = *reinterpret_cast<const float2*>(&qs[c0 + 2][nn]);
            float2 k0 = *reinterpret_cast<const float2*>(&ks[d0 + 0][nn]);
            float2 k1 = *reinterpret_cast<const float2*>(&ks[d0 + 1][nn]);
            float2 k2 = *reinterpret_cast<const float2*>(&ks[d0 + 2][nn]);
            acc[0][0] = fmaf(q0.x, k0.x, fmaf(q0.y, k0.y, acc[0][0]));
            acc[0][1] = fmaf(q0.x, k1.x, fmaf(q0.y, k1.y, acc[0][1]));
            acc[0][2] = fmaf(q0.x, k2.x, fmaf(q0.y, k2.y, acc[0][2]));
            acc[1][0] = fmaf(q1.x, k0.x, fmaf(q1.y, k0.y, acc[1][0]));
            acc[1][1] = fmaf(q1.x, k1.x, fmaf(q1.y, k1.y, acc[1][1]));
            acc[1][2] = fmaf(q1.x, k2.x, fmaf(q1.y, k2.y, acc[1][2]));
            acc[2][0] = fmaf(q2.x, k0.x, fmaf(q2.y, k0.y, acc[2][0]));
            acc[2][1] = fmaf(q2.x, k1.x, fmaf(q2.y, k1.y, acc[2][1]));
            acc[2][2] = fmaf(q2.x, k2.x, fmaf(q2.y, k2.y, acc[2][2]));
        }
        __syncthreads();
#pragma unroll
        for (int j = 0; j < 3; j++) rbuf[j] = rnext[j];
    }

    float* pp = part + (((size_t)ns * B_ + b) * HEADS_ + h) * 2304;
#pragma unroll
    for (int i = 0; i < 3; i++)
#pragma unroll
        for (int j = 0; j < 3; j++) pp[(c0 + i) * 48 + d0 + j] = acc[i][j];
}

// ---------------- reduce partials, scale by rsqrt(sumsq) & temperature, softmax ----------
__global__ void softmax_kernel(const float* __restrict__ part, const float* __restrict__ sumsq,
                               const float* __restrict__ temp, float* __restrict__ attn) {
    int c = blockIdx.x, h = blockIdx.y, b = blockIdx.z;
    int d = threadIdx.x;
    __shared__ float sv[48];
    __shared__ float m_s, sum_s;
    float s = 0.f;
    if (d < 48) {
        const float* pp = part + ((size_t)b * HEADS_ + h) * 2304 + c * 48 + d;
        const size_t stride = (size_t)B_ * HEADS_ * 2304;
        for (int p = 0; p < NSPLIT; p++) s += pp[(size_t)p * stride];
        float rq = 1.f / fmaxf(sqrtf(sumsq[b * 384 + h * 48 + c]), 1e-12f);
        float rk = 1.f / fmaxf(sqrtf(sumsq[b * 384 + 192 + h * 48 + d]), 1e-12f);
        s *= rq * rk * temp[h];
        sv[d] = s;
    }
    __syncthreads();
    if (threadIdx.x == 0) {
        float m = sv[0];
        for (int i = 1; i < 48; i++) m = fmaxf(m, sv[i]);
        m_s = m;
    }
    __syncthreads();
    float e = 0.f;
    if (d < 48) { e = expf(s - m_s); sv[d] = e; }
    __syncthreads();
    if (threadIdx.x == 0) {
        float t2 = 0.f;
        for (int i = 0; i < 48; i++) t2 += sv[i];
        sum_s = t2;
    }
    __syncthreads();
    if (d < 48) attn[(((size_t)b * HEADS_ + h) * 48 + c) * 48 + d] = e / sum_s;
}

// ---------------- M = proj_w @ attn  (per batch; [hd][co] layout) ----------------
__global__ void mm_kernel(const float* __restrict__ proj_w, const float* __restrict__ attn,
                          float* __restrict__ M) {
    __shared__ float at[48][48];   // [c][d]
    __shared__ float pw[48][48];   // [co][c]
    int h = blockIdx.x, b = blockIdx.y;
    int tid = threadIdx.x;
    for (int i = tid; i < 2304; i += 256) {
        int c = i / 48, d = i % 48;
        at[c][d] = attn[((size_t)b * HEADS_ + h) * 2304 + i];
        int co = i / 48, cc = i % 48;
        pw[co][cc] = proj_w[(size_t)co * 192 + h * 48 + cc];
    }
    __syncthreads();
    for (int i = tid; i < 2304; i += 256) {
        int co = i / 48, d = i % 48;
        float s = 0.f;
#pragma unroll 8
        for (int c = 0; c < 48; c++) s = fmaf(pw[co][c], at[c][d], s);
        M[((size_t)b * 192 + h * 48 + d) * 48 + co] = s;
    }
}

// ---------------- out = M @ v + proj_b + x  (fused attn·v + proj + residual) ----------
__global__ void __launch_bounds__(256) avproj_kernel(
        const float* __restrict__ qkv2, const float* __restrict__ M,
        const float* __restrict__ bias, const float* __restrict__ x,
        float* __restrict__ out) {
    __shared__ float Ms[192][48];          // [hd][co]
    int b = blockIdx.y;
    int tid = threadIdx.x;
    for (int i = tid; i < 192 * 48; i += 256)
        (&Ms[0][0])[i] = M[(size_t)b * 192 * 48 + i];
    __syncthreads();
    int n = blockIdx.x * 256 + tid;
    const float* vb = qkv2 + (size_t)(b * 576 + 384) * N_ + n;
    float acc[48];
#pragma unroll
    for (int co = 0; co < 48; co++) acc[co] = bias[co];
#pragma unroll 4
    for (int hd = 0; hd < 192; hd++) {
        float v = vb[(size_t)hd * N_];
        const float4* mr = reinterpret_cast<const float4*>(&Ms[hd][0]);
#pragma unroll
        for (int c4 = 0; c4 < 12; c4++) {
            float4 a = mr[c4];
            acc[c4 * 4 + 0] = fmaf(a.x, v, acc[c4 * 4 + 0]);
            acc[c4 * 4 + 1] = fmaf(a.y, v, acc[c4 * 4 + 1]);
            acc[c4 * 4 + 2] = fmaf(a.z, v, acc[c4 * 4 + 2]);
            acc[c4 * 4 + 3] = fmaf(a.w, v, acc[c4 * 4 + 3]);
        }
    }
    const float* xp = x + (size_t)b * 48 * N_ + n;
    float* op = out + (size_t)b * 48 * N_ + n;
#pragma unroll
    for (int co = 0; co < 48; co++) op[(size_t)co * N_] = acc[co] + xp[(size_t)co * N_];
}

// ---------------- launcher ----------------
extern "C" void kernel_launch(void* const* d_in, const int* in_sizes, int n_in,
                              void* d_out, int out_size) {
    (void)in_sizes; (void)n_in; (void)out_size;
    const float* x      = (const float*)d_in[0];
    const float* ln1_w  = (const float*)d_in[1];
    const float* ln1_b  = (const float*)d_in[2];
    const float* qkv_w  = (const float*)d_in[3];
    const float* qkv_b  = (const float*)d_in[4];
    const float* qkvdw_w= (const float*)d_in[5];
    const float* qkvdw_b= (const float*)d_in[6];
    const float* temper = (const float*)d_in[7];
    const float* proj_w = (const float*)d_in[8];
    const float* proj_b = (const float*)d_in[9];
    const float* ln2_w  = (const float*)d_in[10];
    const float* ln2_b  = (const float*)d_in[11];
    const float* pin_w  = (const float*)d_in[12];
    const float* pin_b  = (const float*)d_in[13];
    const float* dw_w   = (const float*)d_in[14];
    const float* dw_b   = (const float*)d_in[15];
    const float* pout_w = (const float*)d_in[16];
    const float* pout_b = (const float*)d_in[17];
    float* out = (float*)d_out;

    float *qkv, *qkv2, *t192, *ln, *part, *attn, *Mbuf, *sumsq;
    cudaGetSymbolAddress((void**)&qkv,  g_qkv);
    cudaGetSymbolAddress((void**)&qkv2, g_qkv2);
    cudaGetSymbolAddress((void**)&t192, g_t192);
    cudaGetSymbolAddress((void**)&ln,   g_ln);
    cudaGetSymbolAddress((void**)&part, g_part);
    cudaGetSymbolAddress((void**)&attn, g_attn);
    cudaGetSymbolAddress((void**)&Mbuf, g_M);
    cudaGetSymbolAddress((void**)&sumsq,g_sumsq);

    // launch 0: zero sumsq (keeps gdw576 the profiled 4th launch)
    zero_kernel<<<3, 256>>>(sumsq, B_ * 384);

    // ---- attention branch ----
    ln_kernel<<<(B_ * N_) / 256, 256>>>(x, ln1_w, ln1_b, ln);                                   // 1

    conv1x1_kernel<48, 32><<<dim3(N_ / 256, 576 / 32, B_), 256>>>(ln, qkv_w, qkv_b, nullptr, qkv, 576); // 2

    gdw576_kernel<<<B_ * 144 * T_ * 4, 128>>>(qkv, qkvdw_w, qkvdw_b, qkv2, sumsq);              // 3 <- profiled

    qk_kernel<<<dim3(NSPLIT, HEADS_, B_), 256>>>(qkv2, part);                                   // 4

    softmax_kernel<<<dim3(48, HEADS_, B_), 64>>>(part, sumsq, temper, attn);                    // 5

    mm_kernel<<<dim3(HEADS_, B_), 256>>>(proj_w, attn, Mbuf);                                   // 6

    avproj_kernel<<<dim3(N_ / 256, B_), 256>>>(qkv2, Mbuf, proj_b, x, out);                     // 7

    // ---- FFN branch ----
    ln_kernel<<<(B_ * N_) / 256, 256>>>(out, ln2_w, ln2_b, ln);                                 // 8

    conv1x1_kernel<48, 32><<<dim3(N_ / 256, 192 / 32, B_), 256>>>(ln, pin_w, pin_b, nullptr, t192, 192); // 9

    ffn_dw_gate_kernel<<<(B_ * 96 * T_ * 16 * 16) / 256, 256>>>(t192, dw_w, dw_b, qkv);         // 10

    conv1x1_kernel<96, 48><<<dim3(N_ / 256, 1, B_), 256>>>(qkv, pout_w, pout_b, out, out, 48);  // 11
}